// round 10
// baseline (speedup 1.0000x reference)
#include <cuda_runtime.h>
#include <cuda_bf16.h>

// MulticlassDice fused, nibble-packed histograms, 1-CTA/SM version.
// Values in [0,8): 8 classes fit one 32-bit reg as 4-bit nibbles.
// dice[n][c] = (2*inter + 1e-5) / (cnt_in + cnt_tg + 1e-5)
// Output: [total, dice[0..7]] (verified rel_err=0 across R3..R9).

#define NCLS 8
#define PIX (512 * 512)
#define MAXN 8
#define GXB 19            // blocks per sample: 19*8 = 152 blocks ~= 148 SMs
#define BT 1024           // threads per block
#define NSLOT (3 * NCLS)  // 24
#define W32 (PIX / 4)     // 65536 int4 words per sample (int32 view)
#define W64 (PIX / 2)     // 131072 int4 words per sample (int64 view)
#define CH32 ((W32 + GXB - 1) / GXB)  // 3450
#define CH64 ((W64 + GXB - 1) / GXB)  // 6899

__device__ int g_cnt[MAXN][NSLOT];  // zero-init; last block re-zeros
__device__ unsigned int g_done;     // zero-init; last block resets

__device__ __forceinline__ void acc_px(int a, int b, unsigned& hin, unsigned& htg,
                                       unsigned& hxx) {
    unsigned sa = 1u << (4 * a);
    unsigned sb = 1u << (4 * b);
    hin += sa;
    htg += sb;
    if (a == b) hxx += sa;
}

__device__ __forceinline__ void acc4(const int4& va, const int4& vb, unsigned& hin,
                                     unsigned& htg, unsigned& hxx) {
    acc_px(va.x, vb.x, hin, htg, hxx);
    acc_px(va.y, vb.y, hin, htg, hxx);
    acc_px(va.z, vb.z, hin, htg, hxx);
    acc_px(va.w, vb.w, hin, htg, hxx);
}

// nibbles (cap 16) -> byte-packed (cap 256)
__device__ __forceinline__ void drain1(unsigned& h, unsigned& be, unsigned& bo) {
    be += h & 0x0F0F0F0Fu;
    bo += (h >> 4) & 0x0F0F0F0Fu;
    h = 0u;
}

__global__ __launch_bounds__(BT, 1) void k_dice_fused(const int* __restrict__ inB,
                                                      const int* __restrict__ tgB,
                                                      const float* __restrict__ w,
                                                      float* __restrict__ out,
                                                      int out_size, int N) {
    const int n = blockIdx.y;
    const int tid = threadIdx.x;
    const int lid = tid & 31;
    const int wid = tid >> 5;  // 0..31
    const unsigned FULL = 0xffffffffu;

    // ---- detect load issued first; ballot consumed after speculative loads ----
    int odd = __ldg(&inB[2 * lid + 1]);

    // ---- speculative int32-path loads (clamped => safe under either dtype) ----
    const int4* a = (const int4*)inB + (size_t)n * W32;
    const int4* b = (const int4*)tgB + (size_t)n * W32;
    const int start = blockIdx.x * CH32;
    const int end = min(start + CH32, W32);
    const int i0 = start + tid, i1 = i0 + BT, i2 = i0 + 2 * BT, i3 = i0 + 3 * BT;
    const bool v0 = i0 < end, v1 = i1 < end, v2 = i2 < end, v3 = i3 < end;
    const int c0 = min(i0, W32 - 1), c1 = min(i1, W32 - 1);
    const int c2 = min(i2, W32 - 1), c3 = min(i3, W32 - 1);
    int4 a0 = a[c0], b0 = b[c0];
    int4 a1 = a[c1], b1 = b[c1];
    int4 a2 = a[c2], b2 = b[c2];
    int4 a3 = a[c3], b3 = b[c3];

    // ---- barrier-free dtype detect (odd 32-bit words all zero => int64) ----
    unsigned dmask = __ballot_sync(FULL, odd != 0);
    const bool is64 = (dmask == 0u);

    unsigned hin = 0, htg = 0, hxx = 0;
    unsigned be_in = 0, bo_in = 0, be_tg = 0, bo_tg = 0, be_xx = 0, bo_xx = 0;

    if (!is64) {
        // up to 16 px/thread; drain at 8 px to stay under nibble cap 15
        if (v0) acc4(a0, b0, hin, htg, hxx);
        if (v1) acc4(a1, b1, hin, htg, hxx);
        drain1(hin, be_in, bo_in);
        drain1(htg, be_tg, bo_tg);
        drain1(hxx, be_xx, bo_xx);
        if (v2) acc4(a2, b2, hin, htg, hxx);
        if (v3) acc4(a3, b3, hin, htg, hxx);
    } else {
        // int64: 2 px per int4 (low halves .x/.z); <=7 iters -> <=14 per nibble
        const int4* a8 = (const int4*)inB + (size_t)n * W64;
        const int4* b8 = (const int4*)tgB + (size_t)n * W64;
        const int s8 = blockIdx.x * CH64;
        const int e8 = min(s8 + CH64, W64);
        for (int i = s8 + tid; i < e8; i += BT) {
            int4 va = a8[i], vb = b8[i];
            acc_px(va.x, vb.x, hin, htg, hxx);
            acc_px(va.z, vb.z, hin, htg, hxx);
        }
    }
    drain1(hin, be_in, bo_in);
    drain1(htg, be_tg, bo_tg);
    drain1(hxx, be_xx, bo_xx);

    // ---- pack byte counters into 16-bit pairs, 12 REDUX per warp ----
    // per type: r0=(c0,c4), r1=(c2,c6), r2=(c1,c5), r3=(c3,c7); warp sum <= 512/field
    const unsigned M = 0x00FF00FFu;
    unsigned r[12];
    r[0] = be_in & M;  r[1] = (be_in >> 8) & M;
    r[2] = bo_in & M;  r[3] = (bo_in >> 8) & M;
    r[4] = be_tg & M;  r[5] = (be_tg >> 8) & M;
    r[6] = bo_tg & M;  r[7] = (bo_tg >> 8) & M;
    r[8] = be_xx & M;  r[9] = (be_xx >> 8) & M;
    r[10] = bo_xx & M; r[11] = (bo_xx >> 8) & M;
#pragma unroll
    for (int j = 0; j < 12; j++) r[j] = __reduce_add_sync(FULL, r[j]);

    __shared__ unsigned s_ph[32][12];
    if (lid == 0) {
#pragma unroll
        for (int j = 0; j < 12; j++) s_ph[wid][j] = r[j];
    }
    __syncthreads();

    // 24 threads gather across 32 warps, publish to global counters
    if (tid < NSLOT) {
        int t = tid / NCLS, c = tid % NCLS;
        int j = t * 4 + (c & 1) * 2 + ((c >> 1) & 1);
        int h = (c >> 2) * 16;
        int acc = 0;
#pragma unroll
        for (int ww = 0; ww < 32; ww++) acc += (int)((s_ph[ww][j] >> h) & 0xFFFFu);
        atomicAdd(&g_cnt[n][tid], acc);
    }
    __syncthreads();

    // ---- last-block-done via acq_rel atomic ----
    __shared__ bool s_last;
    if (tid == 0) {
        unsigned int* gp = &g_done;
        unsigned int prev;
        asm volatile("atom.add.acq_rel.gpu.u32 %0, [%1], %2;"
                     : "=r"(prev)
                     : "l"(gp), "r"(1u)
                     : "memory");
        s_last = (prev == (unsigned int)(GXB * N - 1));
    }
    __syncthreads();
    if (!s_last) return;

    // ---- epilogue: dice + output + state reset ----
    __shared__ float dice[MAXN][NCLS];
    __shared__ float mean_c[NCLS];
    __shared__ float total_s;
    if (tid < N * NCLS) {
        int nn = tid / NCLS, c = tid % NCLS;
        float inter = (float)g_cnt[nn][2 * NCLS + c];
        float sums = (float)(g_cnt[nn][0 * NCLS + c] + g_cnt[nn][1 * NCLS + c]);
        dice[nn][c] = (2.0f * inter + 1e-5f) / (sums + 1e-5f);
    }
    __syncthreads();
    if (tid < NCLS) {
        float m = 0.0f;
        for (int i = 0; i < N; i++) m += dice[i][tid];
        mean_c[tid] = m / (float)N;
    }
    __syncthreads();
    if (tid == 0) {
        float t = 0.0f;
#pragma unroll
        for (int c = 0; c < NCLS; c++) t += w[c] * mean_c[c];
        total_s = t;
    }
    __syncthreads();

    for (int i = tid; i < out_size; i += BT) {
        float v;
        if (out_size >= NCLS + 1) {
            v = (i == 0) ? total_s : (i <= NCLS ? mean_c[i - 1] : 0.0f);
        } else if (out_size == NCLS) {
            v = mean_c[i];
        } else {
            v = (i == 0) ? total_s : (i - 1 < NCLS ? mean_c[i - 1] : 0.0f);
        }
        out[i] = v;
    }

    // reset for next graph replay (kernel boundary publishes)
    if (tid < MAXN * NSLOT) ((int*)g_cnt)[tid] = 0;
    if (tid == 0) g_done = 0u;
}

extern "C" void kernel_launch(void* const* d_in, const int* in_sizes, int n_in,
                              void* d_out, int out_size) {
    const int* inB = (const int*)d_in[0];
    const int* tgB = (const int*)d_in[1];
    const float* w = (const float*)d_in[2];
    float* out = (float*)d_out;

    int N = in_sizes[0] / PIX;
    if (N < 1) N = 1;
    if (N > MAXN) N = MAXN;

    dim3 grid(GXB, N);
    k_dice_fused<<<grid, BT>>>(inB, tgB, w, out, out_size, N);
}

// round 12
// speedup vs baseline: 1.0962x; 1.0962x over previous
#include <cuda_runtime.h>
#include <cuda_bf16.h>

// MulticlassDice fused, nibble-packed histograms, lean-tail version.
// Inputs proven int32 at runtime (R5 ncu traffic = 16.8 MB = 2 x 8 MB).
// dice[n][c] = (2*inter + 1e-5) / (cnt_in + cnt_tg + 1e-5)
// Output: [total, dice[0..7]] (verified rel_err=0 across R3..R10).

#define NCLS 8
#define PIX (512 * 512)
#define MAXN 8
#define GXB 19            // blocks per sample: 19*8 = 152 ~= 148 SMs
#define BT 1024
#define NSLOT (3 * NCLS)  // 24
#define W32 (PIX / 4)     // 65536 int4 words per sample
#define CH32 ((W32 + GXB - 1) / GXB)  // 3450

__device__ int g_cnt[MAXN][NSLOT];  // zero-init; last block re-zeros
__device__ unsigned int g_done;     // zero-init; last block resets

__device__ __forceinline__ void acc_px(int a, int b, unsigned& hin, unsigned& htg,
                                       unsigned& hxx) {
    unsigned sa = 1u << (4 * a);
    unsigned sb = 1u << (4 * b);
    hin += sa;
    htg += sb;
    if (a == b) hxx += sa;
}

__device__ __forceinline__ void acc4(const int4& va, const int4& vb, unsigned& hin,
                                     unsigned& htg, unsigned& hxx) {
    acc_px(va.x, vb.x, hin, htg, hxx);
    acc_px(va.y, vb.y, hin, htg, hxx);
    acc_px(va.z, vb.z, hin, htg, hxx);
    acc_px(va.w, vb.w, hin, htg, hxx);
}

// nibbles (cap 16) -> byte-packed (cap 256)
__device__ __forceinline__ void drain1(unsigned& h, unsigned& be, unsigned& bo) {
    be += h & 0x0F0F0F0Fu;
    bo += (h >> 4) & 0x0F0F0F0Fu;
    h = 0u;
}

__global__ __launch_bounds__(BT, 1) void k_dice_fused(const int* __restrict__ inB,
                                                      const int* __restrict__ tgB,
                                                      const float* __restrict__ w,
                                                      float* __restrict__ out,
                                                      int out_size, int N) {
    const int n = blockIdx.y;
    const int tid = threadIdx.x;
    const int lid = tid & 31;
    const int wid = tid >> 5;  // 0..31
    const unsigned FULL = 0xffffffffu;

    // ---- mainloop: loads first, all front-batched (8 LDG.128 per thread) ----
    const int4* a = (const int4*)inB + (size_t)n * W32;
    const int4* b = (const int4*)tgB + (size_t)n * W32;
    const int start = blockIdx.x * CH32;
    const int end = min(start + CH32, W32);
    const int i0 = start + tid, i1 = i0 + BT, i2 = i0 + 2 * BT, i3 = i0 + 3 * BT;
    const bool v0 = i0 < end, v1 = i1 < end, v2 = i2 < end, v3 = i3 < end;
    int4 a0, a1, a2, a3, b0, b1, b2, b3;
    if (v0) { a0 = a[i0]; b0 = b[i0]; }
    if (v1) { a1 = a[i1]; b1 = b[i1]; }
    if (v2) { a2 = a[i2]; b2 = b[i2]; }
    if (v3) { a3 = a[i3]; b3 = b[i3]; }

    unsigned hin = 0, htg = 0, hxx = 0;
    unsigned be_in = 0, bo_in = 0, be_tg = 0, bo_tg = 0, be_xx = 0, bo_xx = 0;

    // 16 px/thread max; drain at 8 px to respect nibble cap 15
    if (v0) acc4(a0, b0, hin, htg, hxx);
    if (v1) acc4(a1, b1, hin, htg, hxx);
    drain1(hin, be_in, bo_in);
    drain1(htg, be_tg, bo_tg);
    drain1(hxx, be_xx, bo_xx);
    if (v2) acc4(a2, b2, hin, htg, hxx);
    if (v3) acc4(a3, b3, hin, htg, hxx);
    drain1(hin, be_in, bo_in);
    drain1(htg, be_tg, bo_tg);
    drain1(hxx, be_xx, bo_xx);

    // ---- pack byte counters into 16-bit pairs, 12 REDUX per warp ----
    // per type: r0=(c0,c4), r1=(c2,c6), r2=(c1,c5), r3=(c3,c7)
    const unsigned M = 0x00FF00FFu;
    unsigned r[12];
    r[0] = be_in & M;  r[1] = (be_in >> 8) & M;
    r[2] = bo_in & M;  r[3] = (bo_in >> 8) & M;
    r[4] = be_tg & M;  r[5] = (be_tg >> 8) & M;
    r[6] = bo_tg & M;  r[7] = (bo_tg >> 8) & M;
    r[8] = be_xx & M;  r[9] = (be_xx >> 8) & M;
    r[10] = bo_xx & M; r[11] = (bo_xx >> 8) & M;
#pragma unroll
    for (int j = 0; j < 12; j++) r[j] = __reduce_add_sync(FULL, r[j]);

    __shared__ unsigned s_ph[32][12];
    if (lid == 0) {
#pragma unroll
        for (int j = 0; j < 12; j++) s_ph[wid][j] = r[j];
    }
    __syncthreads();
    if (wid != 0) return;  // warps 1..31 done; warp 0 owns publish + epilogue

    // ---- warp 0: gather 24 slots across 32 warps, publish, release bump ----
    if (lid < NSLOT) {
        int t = lid / NCLS, c = lid % NCLS;
        int j = t * 4 + (c & 1) * 2 + ((c >> 1) & 1);
        int h = (c >> 2) * 16;
        int acc = 0;
#pragma unroll
        for (int ww = 0; ww < 32; ww++) acc += (int)((s_ph[ww][j] >> h) & 0xFFFFu);
        atomicAdd(&g_cnt[n][lid], acc);
    }
    __syncwarp(FULL);

    unsigned prev = 0;
    if (lid == 0) {
        unsigned int* gp = &g_done;
        asm volatile("atom.add.acq_rel.gpu.u32 %0, [%1], %2;"
                     : "=r"(prev)
                     : "l"(gp), "r"(1u)
                     : "memory");
    }
    prev = __shfl_sync(FULL, prev, 0);
    if (prev != (unsigned)(GXB * N - 1)) return;

    // ---- last block, warp 0 only: shuffle-based epilogue ----
    float wc = (lid < NCLS) ? __ldg(&w[lid]) : 0.0f;  // issue early

    // lane l: class c = l&7, covers samples n = l>>3 and n = (l>>3)+4
    const int c = lid & 7;
    const int h0 = lid >> 3;  // 0..3
    float m = 0.0f;
    if (h0 < N) {
        float inter = (float)g_cnt[h0][2 * NCLS + c];
        float sums = (float)(g_cnt[h0][0 * NCLS + c] + g_cnt[h0][1 * NCLS + c]);
        m += (2.0f * inter + 1e-5f) / (sums + 1e-5f);
    }
    if (h0 + 4 < N) {
        float inter = (float)g_cnt[h0 + 4][2 * NCLS + c];
        float sums = (float)(g_cnt[h0 + 4][0 * NCLS + c] + g_cnt[h0 + 4][1 * NCLS + c]);
        m += (2.0f * inter + 1e-5f) / (sums + 1e-5f);
    }
    m += __shfl_xor_sync(FULL, m, 8);
    m += __shfl_xor_sync(FULL, m, 16);
    const float mean = m / (float)N;  // lanes 0..7 hold mean dice for class lid

    // total = sum_c w[c]*mean_c : lanes 0..7 closed under xor {1,2,4}
    float t = (lid < NCLS) ? wc * mean : 0.0f;
    t += __shfl_xor_sync(FULL, t, 1);
    t += __shfl_xor_sync(FULL, t, 2);
    t += __shfl_xor_sync(FULL, t, 4);
    const float total = __shfl_sync(FULL, t, 0);

    if (out_size >= NCLS + 1) {
        if (lid == 0) out[0] = total;
        if (lid < NCLS) out[1 + lid] = mean;  // lane's c == lid for lid<8
        for (int i = NCLS + 1 + lid; i < out_size; i += 32) out[i] = 0.0f;
    } else if (out_size == NCLS) {
        if (lid < NCLS) out[lid] = mean;
    } else {
        if (lid == 0 && out_size > 0) out[0] = total;
        for (int i = 1 + lid; i < out_size; i += 32) out[i] = (i - 1 < NCLS) ? mean : 0.0f;
    }

    // ---- reset state for next graph replay (kernel boundary publishes) ----
    for (int i = lid; i < MAXN * NSLOT; i += 32) ((int*)g_cnt)[i] = 0;
    if (lid == 0) g_done = 0u;
}

extern "C" void kernel_launch(void* const* d_in, const int* in_sizes, int n_in,
                              void* d_out, int out_size) {
    const int* inB = (const int*)d_in[0];
    const int* tgB = (const int*)d_in[1];
    const float* w = (const float*)d_in[2];
    float* out = (float*)d_out;

    int N = in_sizes[0] / PIX;
    if (N < 1) N = 1;
    if (N > MAXN) N = MAXN;

    dim3 grid(GXB, N);
    k_dice_fused<<<grid, BT>>>(inB, tgB, w, out, out_size, N);
}

// round 13
// speedup vs baseline: 1.2574x; 1.1471x over previous
#include <cuda_runtime.h>
#include <cuda_bf16.h>

// MulticlassDice fused: nibble-packed histograms, R8 geometry (592x256) +
// R12 lean tail (early warp exit, single-warp shuffle epilogue).
// Inputs proven int32 at runtime (R5 ncu traffic = 16.8 MB = 2 x 8 MB).
// dice[n][c] = (2*inter + 1e-5) / (cnt_in + cnt_tg + 1e-5)
// Output: [total, dice[0..7]] (verified across R3..R12).

#define NCLS 8
#define PIX (512 * 512)
#define MAXN 8
#define GXB 74            // blocks per sample: 74*8 = 592 = 4/SM on 148 SMs
#define BT 256
#define NWARP (BT / 32)   // 8
#define NSLOT (3 * NCLS)  // 24
#define W32 (PIX / 4)     // 65536 int4 words per sample
#define CH32 ((W32 + GXB - 1) / GXB)  // 886

__device__ int g_cnt[MAXN][NSLOT];  // zero-init; last block re-zeros
__device__ unsigned int g_done;     // zero-init; last block resets

__device__ __forceinline__ void acc_px(int a, int b, unsigned& hin, unsigned& htg,
                                       unsigned& hxx) {
    unsigned sa = 1u << (4 * a);
    unsigned sb = 1u << (4 * b);
    hin += sa;
    htg += sb;
    if (a == b) hxx += sa;
}

__device__ __forceinline__ void acc4(const int4& va, const int4& vb, unsigned& hin,
                                     unsigned& htg, unsigned& hxx) {
    acc_px(va.x, vb.x, hin, htg, hxx);
    acc_px(va.y, vb.y, hin, htg, hxx);
    acc_px(va.z, vb.z, hin, htg, hxx);
    acc_px(va.w, vb.w, hin, htg, hxx);
}

// nibbles (cap 16) -> byte-packed (cap 256)
__device__ __forceinline__ void drain1(unsigned& h, unsigned& be, unsigned& bo) {
    be += h & 0x0F0F0F0Fu;
    bo += (h >> 4) & 0x0F0F0F0Fu;
    h = 0u;
}

__global__ __launch_bounds__(BT, 4) void k_dice_fused(const int* __restrict__ inB,
                                                      const int* __restrict__ tgB,
                                                      const float* __restrict__ w,
                                                      float* __restrict__ out,
                                                      int out_size, int N) {
    const int n = blockIdx.y;
    const int tid = threadIdx.x;
    const int lid = tid & 31;
    const int wid = tid >> 5;  // 0..7
    const unsigned FULL = 0xffffffffu;

    // ---- mainloop: loads first, all front-batched (8 LDG.128 per thread) ----
    const int4* a = (const int4*)inB + (size_t)n * W32;
    const int4* b = (const int4*)tgB + (size_t)n * W32;
    const int start = blockIdx.x * CH32;
    const int end = min(start + CH32, W32);
    const int i0 = start + tid, i1 = i0 + BT, i2 = i0 + 2 * BT, i3 = i0 + 3 * BT;
    const bool v0 = i0 < end, v1 = i1 < end, v2 = i2 < end, v3 = i3 < end;
    int4 a0, a1, a2, a3, b0, b1, b2, b3;
    if (v0) { a0 = a[i0]; b0 = b[i0]; }
    if (v1) { a1 = a[i1]; b1 = b[i1]; }
    if (v2) { a2 = a[i2]; b2 = b[i2]; }
    if (v3) { a3 = a[i3]; b3 = b[i3]; }

    unsigned hin = 0, htg = 0, hxx = 0;
    unsigned be_in = 0, bo_in = 0, be_tg = 0, bo_tg = 0, be_xx = 0, bo_xx = 0;

    // 16 px/thread max; drain at 8 px to respect nibble cap 15
    if (v0) acc4(a0, b0, hin, htg, hxx);
    if (v1) acc4(a1, b1, hin, htg, hxx);
    drain1(hin, be_in, bo_in);
    drain1(htg, be_tg, bo_tg);
    drain1(hxx, be_xx, bo_xx);
    if (v2) acc4(a2, b2, hin, htg, hxx);
    if (v3) acc4(a3, b3, hin, htg, hxx);
    drain1(hin, be_in, bo_in);
    drain1(htg, be_tg, bo_tg);
    drain1(hxx, be_xx, bo_xx);

    // ---- pack byte counters into 16-bit pairs, 12 REDUX per warp ----
    // per type: r0=(c0,c4), r1=(c2,c6), r2=(c1,c5), r3=(c3,c7)
    const unsigned M = 0x00FF00FFu;
    unsigned r[12];
    r[0] = be_in & M;  r[1] = (be_in >> 8) & M;
    r[2] = bo_in & M;  r[3] = (bo_in >> 8) & M;
    r[4] = be_tg & M;  r[5] = (be_tg >> 8) & M;
    r[6] = bo_tg & M;  r[7] = (bo_tg >> 8) & M;
    r[8] = be_xx & M;  r[9] = (be_xx >> 8) & M;
    r[10] = bo_xx & M; r[11] = (bo_xx >> 8) & M;
#pragma unroll
    for (int j = 0; j < 12; j++) r[j] = __reduce_add_sync(FULL, r[j]);

    __shared__ unsigned s_ph[NWARP][12];
    if (lid == 0) {
#pragma unroll
        for (int j = 0; j < 12; j++) s_ph[wid][j] = r[j];
    }
    __syncthreads();
    if (wid != 0) return;  // warps 1..7 done; warp 0 owns publish + epilogue

    // ---- warp 0: gather 24 slots across 8 warps, publish, release bump ----
    if (lid < NSLOT) {
        int t = lid / NCLS, c = lid % NCLS;
        int j = t * 4 + (c & 1) * 2 + ((c >> 1) & 1);
        int h = (c >> 2) * 16;
        int acc = 0;
#pragma unroll
        for (int ww = 0; ww < NWARP; ww++) acc += (int)((s_ph[ww][j] >> h) & 0xFFFFu);
        atomicAdd(&g_cnt[n][lid], acc);
    }
    __syncwarp(FULL);

    unsigned prev = 0;
    if (lid == 0) {
        unsigned int* gp = &g_done;
        asm volatile("atom.add.acq_rel.gpu.u32 %0, [%1], %2;"
                     : "=r"(prev)
                     : "l"(gp), "r"(1u)
                     : "memory");
    }
    prev = __shfl_sync(FULL, prev, 0);
    if (prev != (unsigned)(GXB * N - 1)) return;

    // ---- last block, warp 0 only: shuffle-based epilogue ----
    float wc = (lid < NCLS) ? __ldg(&w[lid]) : 0.0f;  // issue early

    // lane l: class c = l&7, covers samples n = l>>3 and n = (l>>3)+4
    const int c = lid & 7;
    const int h0 = lid >> 3;  // 0..3
    float m = 0.0f;
    if (h0 < N) {
        float inter = (float)g_cnt[h0][2 * NCLS + c];
        float sums = (float)(g_cnt[h0][0 * NCLS + c] + g_cnt[h0][1 * NCLS + c]);
        m += (2.0f * inter + 1e-5f) / (sums + 1e-5f);
    }
    if (h0 + 4 < N) {
        float inter = (float)g_cnt[h0 + 4][2 * NCLS + c];
        float sums = (float)(g_cnt[h0 + 4][0 * NCLS + c] + g_cnt[h0 + 4][1 * NCLS + c]);
        m += (2.0f * inter + 1e-5f) / (sums + 1e-5f);
    }
    m += __shfl_xor_sync(FULL, m, 8);
    m += __shfl_xor_sync(FULL, m, 16);
    const float mean = m / (float)N;  // lanes 0..7 hold mean dice for class lid

    // total = sum_c w[c]*mean_c : lanes 0..7 closed under xor {1,2,4}
    float t = (lid < NCLS) ? wc * mean : 0.0f;
    t += __shfl_xor_sync(FULL, t, 1);
    t += __shfl_xor_sync(FULL, t, 2);
    t += __shfl_xor_sync(FULL, t, 4);
    const float total = __shfl_sync(FULL, t, 0);

    if (out_size >= NCLS + 1) {
        if (lid == 0) out[0] = total;
        if (lid < NCLS) out[1 + lid] = mean;  // lane's c == lid for lid<8
        for (int i = NCLS + 1 + lid; i < out_size; i += 32) out[i] = 0.0f;
    } else if (out_size == NCLS) {
        if (lid < NCLS) out[lid] = mean;
    } else {
        if (lid == 0 && out_size > 0) out[0] = total;
        for (int i = 1 + lid; i < out_size; i += 32) out[i] = (i - 1 < NCLS) ? mean : 0.0f;
    }

    // ---- reset state for next graph replay (kernel boundary publishes) ----
    for (int i = lid; i < MAXN * NSLOT; i += 32) ((int*)g_cnt)[i] = 0;
    if (lid == 0) g_done = 0u;
}

extern "C" void kernel_launch(void* const* d_in, const int* in_sizes, int n_in,
                              void* d_out, int out_size) {
    const int* inB = (const int*)d_in[0];
    const int* tgB = (const int*)d_in[1];
    const float* w = (const float*)d_in[2];
    float* out = (float*)d_out;

    int N = in_sizes[0] / PIX;
    if (N < 1) N = 1;
    if (N > MAXN) N = MAXN;

    dim3 grid(GXB, N);
    k_dice_fused<<<grid, BT>>>(inB, tgB, w, out, out_size, N);
}